// round 15
// baseline (speedup 1.0000x reference)
#include <cuda_runtime.h>
#include <cstdint>

// EfficientByteMUL — driver memcpy for the bulk copy + tiny patch kernel.
// Layout: MARK_AX=0, OP_MUL=1, ALU_LO=16, ALU_HI=32, AX_CARRY_LO=48, AX_CARRY_HI=64,
// OUTPUT_LO=80, OUTPUT_HI=96, BD_DIM=128. GE pos-0 input is 3-sparse:
//   h_j = relu(a*W1[0,j] + b*W1[1,j] + W1[29,j] + b1[j]),  y = sum_j h_j*W2[j,40] + b2[40]
//
// out = x everywhere except two elements per ACTIVE token, and those two are
// out[e] = x[e] + 2.0 (computable from x alone). So:
//   node 1: cudaMemcpyAsync(out, x, 32MB, D2D)   -- driver-tuned copy
//   node 2: patch kernel -- reads masks (8B/token), processes active tokens,
//           stores the two patched elements directly (no RMW on out).

// 32 tokens per warp-task; 256 CTAs x 8 warps = 2048 warps = 65536/32 tasks, one each.
#define PATCH_CTAS 256

__global__ void __launch_bounds__(256)
patch_kernel(const float* __restrict__ x,
             float* __restrict__ out,
             const float* __restrict__ W1,
             const float* __restrict__ b1,
             const float* __restrict__ W2,
             const float* __restrict__ b2,
             int n_tokens)
{
    __shared__ __align__(16) float4 s_coeff[256];
    __shared__ float s_b2;

    const unsigned FULL = 0xffffffffu;
    int tid  = threadIdx.x;
    int warp = tid >> 5;
    int lane = tid & 31;

    // Build coefficient table: s_coeff[j] = (W1[0,j], W1[1,j], W1[29,j]+b1[j], W2[j,40])
    s_coeff[tid] = make_float4(W1[tid], W1[256 + tid],
                               W1[29 * 256 + tid] + b1[tid], W2[tid * 64 + 40]);
    if (tid == 0) s_b2 = b2[40];
    __syncthreads();
    float b2v = s_b2;

    int task = blockIdx.x * 8 + warp;           // 0..2047
    int ntasks = (n_tokens + 31) >> 5;

    for (; task < ntasks; task += gridDim.x * 8) {
        int tbase = task * 32;

        // Each lane checks one token's mask pair (elems 0,1) — sector-granular reads,
        // L2-hot behind the memcpy.
        bool pred = false;
        int t = tbase + lane;
        if (t < n_tokens) {
            float2 m = *reinterpret_cast<const float2*>(x + (size_t)t * 128);
            pred = (m.x >= 0.5f) && (m.y >= 0.5f);
        }
        unsigned act = __ballot_sync(FULL, pred);

        while (act) {
            int b = __ffs(act) - 1;
            act &= act - 1;
            const float* xtok = x + (size_t)(tbase + b) * 128;
            float*       otok = out + (size_t)(tbase + b) * 128;

            // argmax over four 16-elem segments: [16,32)->lanes4..7, [32,48)->8..11,
            // [48,64)->12..15, [64,80)->16..19 (first-max wins: strict >, tie -> lower)
            float4 w = make_float4(0.f, 0.f, 0.f, 0.f);
            if (lane >= 4 && lane < 20)
                w = reinterpret_cast<const float4*>(xtok)[lane];

            float best = w.x; int bidx = 0;
            if (w.y > best) { best = w.y; bidx = 1; }
            if (w.z > best) { best = w.z; bidx = 2; }
            if (w.w > best) { best = w.w; bidx = 3; }
            int gidx = ((lane & 3) << 2) | bidx;

            #pragma unroll
            for (int off = 1; off <= 2; off <<= 1) {
                float ob = __shfl_xor_sync(FULL, best, off);
                int   oi = __shfl_xor_sync(FULL, gidx, off);
                if (ob > best || (ob == best && oi < gidx)) { best = ob; gidx = oi; }
            }

            int a_lo = __shfl_sync(FULL, gidx, 4);
            int a_hi = __shfl_sync(FULL, gidx, 8);
            int b_lo = __shfl_sync(FULL, gidx, 12);
            int b_hi = __shfl_sync(FULL, gidx, 16);

            float fa = (float)(a_lo | (a_hi << 4));
            float fb = (float)(b_lo | (b_hi << 4));

            // MLP: j = lane + 32*i, conflict-free LDS.128 from smem table
            float acc = 0.0f;
            #pragma unroll
            for (int i = 0; i < 8; i++) {
                float4 c = s_coeff[lane + 32 * i];
                float h = fmaf(fa, c.x, fmaf(fb, c.y, c.z));
                h = fmaxf(h, 0.0f);
                acc = fmaf(h, c.w, acc);
            }
            #pragma unroll
            for (int off = 16; off; off >>= 1)
                acc += __shfl_xor_sync(FULL, acc, off);
            acc += b2v;

            int res = ((int)rintf(acc)) & 255;   // rintf == round-half-even == jnp.round
            int e_lo = 80 + (res & 15);
            int e_hi = 96 + (res >> 4);

            // Direct store of the patched value (computed from x) — runs after memcpy,
            // so it safely overwrites the copied value. Two lanes do the two stores.
            if (lane == 0) otok[e_lo] = xtok[e_lo] + 2.0f;
            if (lane == 1) otok[e_hi] = xtok[e_hi] + 2.0f;
        }
    }
}

extern "C" void kernel_launch(void* const* d_in, const int* in_sizes, int n_in,
                              void* d_out, int out_size)
{
    const float* x  = (const float*)d_in[0];  // [8, 8192, 128]
    const float* W1 = (const float*)d_in[1];  // [64, 256]
    const float* b1 = (const float*)d_in[2];  // [256]
    const float* W2 = (const float*)d_in[3];  // [256, 64]
    const float* b2 = (const float*)d_in[4];  // [64]
    float* out = (float*)d_out;

    int n_tokens = in_sizes[0] / 128;         // 65536
    size_t bytes = (size_t)in_sizes[0] * sizeof(float);   // 32 MB

    // Bulk copy: driver-tuned D2D copy (graph-capturable, allowed by harness).
    cudaMemcpyAsync(out, x, bytes, cudaMemcpyDeviceToDevice, 0);

    // Patch active tokens (ordered after the copy on the same stream).
    patch_kernel<<<PATCH_CTAS, 256>>>(x, out, W1, b1, W2, b2, n_tokens);
}

// round 17
// speedup vs baseline: 1.2162x; 1.2162x over previous
#include <cuda_runtime.h>
#include <cstdint>

// EfficientByteMUL — driver D2D memcpy (bulk) + high-parallelism patch kernel.
// Layout: MARK_AX=0, OP_MUL=1, ALU_LO=16, ALU_HI=32, AX_CARRY_LO=48, AX_CARRY_HI=64,
// OUTPUT_LO=80, OUTPUT_HI=96, BD_DIM=128. GE pos-0 input is 3-sparse:
//   h_j = relu(a*W1[0,j] + b*W1[1,j] + W1[29,j] + b1[j]),  y = sum_j h_j*W2[j,40] + b2[40]
//
//   node 1: cudaMemcpyAsync(out, x, 32MB, D2D)  -- driver-tuned copy
//   node 2: patch kernel — 4 tokens per warp (16384 warps), avg ~1 active token
//           per warp, each processed by the full warp; stores out[e]=x[e]+2.

#define PATCH_CTAS 2048   // x 8 warps = 16384 warps; 4 tokens/warp = 65536 tokens

__global__ void __launch_bounds__(256)
patch_kernel(const float* __restrict__ x,
             float* __restrict__ out,
             const float* __restrict__ W1,
             const float* __restrict__ b1,
             const float* __restrict__ W2,
             const float* __restrict__ b2,
             int n_tokens)
{
    __shared__ __align__(16) float4 s_coeff[256];
    __shared__ float s_b2;

    const unsigned FULL = 0xffffffffu;
    int tid  = threadIdx.x;
    int warp = tid >> 5;
    int lane = tid & 31;

    // Coefficient table: s_coeff[j] = (W1[0,j], W1[1,j], W1[29,j]+b1[j], W2[j,40])
    s_coeff[tid] = make_float4(W1[tid], W1[256 + tid],
                               W1[29 * 256 + tid] + b1[tid],
                               W2[tid * 64 + 40]);
    if (tid == 0) s_b2 = b2[40];
    __syncthreads();
    float b2v = s_b2;

    int tbase = (blockIdx.x * 8 + warp) * 4;    // this warp's 4 tokens
    if (tbase >= n_tokens) return;

    // lanes 0..3 read mask pairs (elems 0,1 of each token)
    bool pred = false;
    if (lane < 4) {
        int t = tbase + lane;
        if (t < n_tokens) {
            float2 m = *reinterpret_cast<const float2*>(x + (size_t)t * 128);
            pred = (m.x >= 0.5f) && (m.y >= 0.5f);
        }
    }
    unsigned act = __ballot_sync(FULL, pred) & 0xFu;

    while (act) {
        int b = __ffs(act) - 1;
        act &= act - 1;
        const float* xtok = x   + (size_t)(tbase + b) * 128;
        float*       otok = out + (size_t)(tbase + b) * 128;

        // argmax over four 16-elem segments: [16,32)->lanes4..7, [32,48)->8..11,
        // [48,64)->12..15, [64,80)->16..19 (first-max wins: strict >, tie -> lower)
        float4 w = make_float4(0.f, 0.f, 0.f, 0.f);
        if (lane >= 4 && lane < 20)
            w = reinterpret_cast<const float4*>(xtok)[lane];

        float best = w.x; int bidx = 0;
        if (w.y > best) { best = w.y; bidx = 1; }
        if (w.z > best) { best = w.z; bidx = 2; }
        if (w.w > best) { best = w.w; bidx = 3; }
        int gidx = ((lane & 3) << 2) | bidx;

        #pragma unroll
        for (int off = 1; off <= 2; off <<= 1) {
            float ob = __shfl_xor_sync(FULL, best, off);
            int   oi = __shfl_xor_sync(FULL, gidx, off);
            if (ob > best || (ob == best && oi < gidx)) { best = ob; gidx = oi; }
        }

        int a_lo = __shfl_sync(FULL, gidx, 4);
        int a_hi = __shfl_sync(FULL, gidx, 8);
        int b_lo = __shfl_sync(FULL, gidx, 12);
        int b_hi = __shfl_sync(FULL, gidx, 16);

        float fa = (float)(a_lo | (a_hi << 4));
        float fb = (float)(b_lo | (b_hi << 4));

        // MLP: j = lane + 32*i, conflict-free LDS.128 from smem table
        float acc = 0.0f;
        #pragma unroll
        for (int i = 0; i < 8; i++) {
            float4 c = s_coeff[lane + 32 * i];
            float h = fmaf(fa, c.x, fmaf(fb, c.y, c.z));
            h = fmaxf(h, 0.0f);
            acc = fmaf(h, c.w, acc);
        }
        #pragma unroll
        for (int off = 16; off; off >>= 1)
            acc += __shfl_xor_sync(FULL, acc, off);
        acc += b2v;

        int res = ((int)rintf(acc)) & 255;   // rintf == round-half-even == jnp.round
        int e_lo = 80 + (res & 15);
        int e_hi = 96 + (res >> 4);

        // Patched values computed from x; these stores land after the memcpy node.
        if (lane == 0) otok[e_lo] = xtok[e_lo] + 2.0f;
        if (lane == 1) otok[e_hi] = xtok[e_hi] + 2.0f;
    }
}

extern "C" void kernel_launch(void* const* d_in, const int* in_sizes, int n_in,
                              void* d_out, int out_size)
{
    const float* x  = (const float*)d_in[0];  // [8, 8192, 128]
    const float* W1 = (const float*)d_in[1];  // [64, 256]
    const float* b1 = (const float*)d_in[2];  // [256]
    const float* W2 = (const float*)d_in[3];  // [256, 64]
    const float* b2 = (const float*)d_in[4];  // [64]
    float* out = (float*)d_out;

    int n_tokens = in_sizes[0] / 128;         // 65536
    size_t bytes = (size_t)in_sizes[0] * sizeof(float);   // 32 MB

    // Bulk copy: driver-tuned D2D copy (graph-capturable, allowed by harness).
    cudaMemcpyAsync(out, x, bytes, cudaMemcpyDeviceToDevice, 0);

    // Patch active tokens (same stream -> ordered after the copy).
    patch_kernel<<<PATCH_CTAS, 256>>>(x, out, W1, b1, W2, b2, n_tokens);
}